// round 1
// baseline (speedup 1.0000x reference)
#include <cuda_runtime.h>
#include <math.h>

#define BSZ 16
#define CCH 512
#define NPIX 1024
#define NG 32

// Scratch (allocation-free rule => __device__ globals)
__device__ float g_h[(long)BSZ * CCH * NPIX];          // 33.5 MB
__device__ float g_qkv[(long)BSZ * 3 * CCH * NPIX];    // 100 MB
__device__ float g_attn[(long)BSZ * NPIX * NPIX];      // 67 MB
__device__ float g_o[(long)BSZ * CCH * NPIX];          // 33.5 MB

__global__ void groupnorm_kernel(const float* __restrict__ x,
                                 const float* __restrict__ w,
                                 const float* __restrict__ bb,
                                 float* __restrict__ h) {
    int blk = blockIdx.x;            // b*NG + g
    int b = blk / NG, g = blk % NG;
    const int CPG = CCH / NG;        // 16
    const int LEN = CPG * NPIX;      // 16384
    const float* xp = x + ((long)b * CCH + g * CPG) * NPIX;
    float* hp = h + ((long)b * CCH + g * CPG) * NPIX;

    float s = 0.f, s2 = 0.f;
    for (int i = threadIdx.x; i < LEN; i += blockDim.x) {
        float v = xp[i];
        s += v; s2 += v * v;
    }
    __shared__ float sh_s[256], sh_s2[256];
    sh_s[threadIdx.x] = s; sh_s2[threadIdx.x] = s2;
    __syncthreads();
    for (int st = 128; st > 0; st >>= 1) {
        if (threadIdx.x < st) {
            sh_s[threadIdx.x]  += sh_s[threadIdx.x + st];
            sh_s2[threadIdx.x] += sh_s2[threadIdx.x + st];
        }
        __syncthreads();
    }
    float mean = sh_s[0] / (float)LEN;
    float var  = sh_s2[0] / (float)LEN - mean * mean;
    float inv  = rsqrtf(var + 1e-5f);
    for (int i = threadIdx.x; i < LEN; i += blockDim.x) {
        int c = g * CPG + (i >> 10);
        hp[i] = (xp[i] - mean) * inv * w[c] + bb[c];
    }
}

// Generic batched tiled SGEMM: C[b][i,j] = scale * sum_k A[i,k]*B[k,j] (+bias[i]) (+resid)
// A element at A + b*sAb + i*sAi + k*sAk ; B element at B + b*sBb + k*sBk + j*sBj
// C row-major MxN per batch with batch stride sCb. M,N multiples of 64; K multiple of 16.
__global__ void sgemm64(const float* __restrict__ A, const float* __restrict__ Bm,
                        float* __restrict__ Cm,
                        const float* __restrict__ bias, const float* __restrict__ resid,
                        int M, int Nn, int K,
                        long sAi, long sAk, long sAb,
                        long sBk, long sBj, long sBb,
                        long sCb, long sRb, float scale) {
    __shared__ float As[16][65];
    __shared__ float Bs[16][65];
    int b  = blockIdx.z;
    int i0 = blockIdx.y * 64;
    int j0 = blockIdx.x * 64;
    const float* Ab = A + (long)b * sAb;
    const float* Bb = Bm + (long)b * sBb;
    int tid = threadIdx.y * 16 + threadIdx.x;

    float acc[4][4] = {};
    for (int k0 = 0; k0 < K; k0 += 16) {
#pragma unroll
        for (int l = 0; l < 4; l++) {
            int idx = tid + l * 256;
            int ii = idx & 63, kk = idx >> 6;
            As[kk][ii] = Ab[(long)(i0 + ii) * sAi + (long)(k0 + kk) * sAk];
            Bs[kk][ii] = Bb[(long)(k0 + kk) * sBk + (long)(j0 + ii) * sBj];
        }
        __syncthreads();
#pragma unroll
        for (int kk = 0; kk < 16; kk++) {
            float ra[4], rb[4];
#pragma unroll
            for (int r = 0; r < 4; r++) ra[r] = As[kk][threadIdx.y * 4 + r];
#pragma unroll
            for (int s = 0; s < 4; s++) rb[s] = Bs[kk][threadIdx.x * 4 + s];
#pragma unroll
            for (int r = 0; r < 4; r++)
#pragma unroll
                for (int s = 0; s < 4; s++)
                    acc[r][s] += ra[r] * rb[s];
        }
        __syncthreads();
    }

    float* Cb = Cm + (long)b * sCb;
    const float* Rb = resid ? resid + (long)b * sRb : nullptr;
#pragma unroll
    for (int r = 0; r < 4; r++) {
        int i = i0 + threadIdx.y * 4 + r;
        float bv = bias ? bias[i] : 0.f;
#pragma unroll
        for (int s = 0; s < 4; s++) {
            int j = j0 + threadIdx.x * 4 + s;
            float v = acc[r][s] * scale + bv;
            if (Rb) v += Rb[(long)i * Nn + j];
            Cb[(long)i * Nn + j] = v;
        }
    }
}

__global__ void softmax_kernel(float* __restrict__ attn) {
    float* row = attn + (long)blockIdx.x * NPIX;
    int t = threadIdx.x;  // 256 threads, 4 elems each
    float v[4];
    float mx = -1e30f;
#pragma unroll
    for (int l = 0; l < 4; l++) { v[l] = row[t + l * 256]; mx = fmaxf(mx, v[l]); }
    __shared__ float sh[256];
    sh[t] = mx; __syncthreads();
    for (int st = 128; st > 0; st >>= 1) {
        if (t < st) sh[t] = fmaxf(sh[t], sh[t + st]);
        __syncthreads();
    }
    mx = sh[0]; __syncthreads();
    float sum = 0.f;
#pragma unroll
    for (int l = 0; l < 4; l++) { v[l] = __expf(v[l] - mx); sum += v[l]; }
    sh[t] = sum; __syncthreads();
    for (int st = 128; st > 0; st >>= 1) {
        if (t < st) sh[t] += sh[t + st];
        __syncthreads();
    }
    float inv = 1.f / sh[0];
#pragma unroll
    for (int l = 0; l < 4; l++) row[t + l * 256] = v[l] * inv;
}

extern "C" void kernel_launch(void* const* d_in, const int* in_sizes, int n_in,
                              void* d_out, int out_size) {
    const float* x     = (const float*)d_in[0];
    const float* gn_w  = (const float*)d_in[1];
    const float* gn_b  = (const float*)d_in[2];
    const float* qkv_w = (const float*)d_in[3];
    const float* qkv_b = (const float*)d_in[4];
    const float* out_w = (const float*)d_in[5];
    const float* out_b = (const float*)d_in[6];
    float* out = (float*)d_out;

    float *h, *qkv, *attn, *o;
    cudaGetSymbolAddress((void**)&h, g_h);
    cudaGetSymbolAddress((void**)&qkv, g_qkv);
    cudaGetSymbolAddress((void**)&attn, g_attn);
    cudaGetSymbolAddress((void**)&o, g_o);

    const long sH  = (long)CCH * NPIX;       // 512*1024
    const long sQ  = (long)3 * CCH * NPIX;   // 1536*1024
    const long sAt = (long)NPIX * NPIX;      // 1024*1024

    // 1) GroupNorm
    groupnorm_kernel<<<BSZ * NG, 256>>>(x, gn_w, gn_b, h);

    dim3 thr(16, 16);

    // 2) QKV = qkv_w[1536,512] @ h[b][512,1024] + qkv_b
    sgemm64<<<dim3(NPIX / 64, (3 * CCH) / 64, BSZ), thr>>>(
        qkv_w, h, qkv, qkv_b, nullptr,
        3 * CCH, NPIX, CCH,
        /*A*/ 512, 1, 0,
        /*B*/ 1024, 1, sH,
        /*C*/ sQ, 0, 1.0f);

    // 3) scores[n,m] = (1/sqrt(C)) * sum_c q[c,n]*k[c,m]
    sgemm64<<<dim3(NPIX / 64, NPIX / 64, BSZ), thr>>>(
        qkv /*q*/, qkv + (long)CCH * NPIX /*k*/, attn, nullptr, nullptr,
        NPIX, NPIX, CCH,
        /*A: i=n stride 1, k=c stride 1024*/ 1, 1024, sQ,
        /*B: k=c stride 1024, j=m stride 1*/ 1024, 1, sQ,
        /*C*/ sAt, 0, 1.0f / sqrtf((float)CCH));

    // 4) row softmax over m
    softmax_kernel<<<BSZ * NPIX, 256>>>(attn);

    // 5) o[c,n] = sum_m v[c,m] * attn[n,m]
    sgemm64<<<dim3(NPIX / 64, CCH / 64, BSZ), thr>>>(
        qkv + 2L * CCH * NPIX /*v*/, attn, o, nullptr, nullptr,
        CCH, NPIX, NPIX,
        /*A: i=c stride 1024, k=m stride 1*/ 1024, 1, sQ,
        /*B: k=m stride 1, j=n stride 1024*/ 1, 1024, sAt,
        /*C*/ sH, 0, 1.0f);

    // 6) out = x + out_w[512,512] @ o[b][512,1024] + out_b
    sgemm64<<<dim3(NPIX / 64, CCH / 64, BSZ), thr>>>(
        out_w, o, out, out_b, x,
        CCH, NPIX, CCH,
        /*A*/ 512, 1, 0,
        /*B*/ 1024, 1, sH,
        /*C*/ sH, sH, 1.0f);
}

// round 2
// speedup vs baseline: 2.5872x; 2.5872x over previous
#include <cuda_runtime.h>
#include <math.h>
#include <stdint.h>

#define BSZ 16
#define CCH 512
#define NPIX 1024
#define NG 32

// Scratch (allocation-free rule => __device__ globals)
__device__ float g_h[(long)BSZ * CCH * NPIX];          // 33.5 MB
__device__ float g_qkv[(long)BSZ * 3 * CCH * NPIX];    // 100 MB
__device__ float g_attn[(long)BSZ * NPIX * NPIX];      // 67 MB
__device__ float g_o[(long)BSZ * CCH * NPIX];          // 33.5 MB

__global__ void groupnorm_kernel(const float* __restrict__ x,
                                 const float* __restrict__ w,
                                 const float* __restrict__ bb,
                                 float* __restrict__ h) {
    int blk = blockIdx.x;            // b*NG + g
    int b = blk / NG, g = blk % NG;
    const int CPG = CCH / NG;        // 16
    const int LEN = CPG * NPIX;      // 16384
    const float* xp = x + ((long)b * CCH + g * CPG) * NPIX;
    float* hp = h + ((long)b * CCH + g * CPG) * NPIX;

    float s = 0.f, s2 = 0.f;
    for (int i = threadIdx.x; i < LEN; i += blockDim.x) {
        float v = xp[i];
        s += v; s2 += v * v;
    }
    __shared__ float sh_s[256], sh_s2[256];
    sh_s[threadIdx.x] = s; sh_s2[threadIdx.x] = s2;
    __syncthreads();
    for (int st = 128; st > 0; st >>= 1) {
        if (threadIdx.x < st) {
            sh_s[threadIdx.x]  += sh_s[threadIdx.x + st];
            sh_s2[threadIdx.x] += sh_s2[threadIdx.x + st];
        }
        __syncthreads();
    }
    float mean = sh_s[0] / (float)LEN;
    float var  = sh_s2[0] / (float)LEN - mean * mean;
    float inv  = rsqrtf(var + 1e-5f);
    for (int i = threadIdx.x; i < LEN; i += blockDim.x) {
        int c = g * CPG + (i >> 10);
        hp[i] = (xp[i] - mean) * inv * w[c] + bb[c];
    }
}

__device__ __forceinline__ uint32_t f2tf32(float f) {
    uint32_t r;
    asm("cvt.rna.tf32.f32 %0, %1;" : "=r"(r) : "f"(f));
    return r;
}

__device__ __forceinline__ void mma_tf32(float* c,
                                         uint32_t a0, uint32_t a1, uint32_t a2, uint32_t a3,
                                         uint32_t b0, uint32_t b1) {
    asm volatile(
        "mma.sync.aligned.m16n8k8.row.col.f32.tf32.tf32.f32 "
        "{%0,%1,%2,%3}, {%4,%5,%6,%7}, {%8,%9}, {%0,%1,%2,%3};\n"
        : "+f"(c[0]), "+f"(c[1]), "+f"(c[2]), "+f"(c[3])
        : "r"(a0), "r"(a1), "r"(a2), "r"(a3), "r"(b0), "r"(b1));
}

// Generic batched tf32 tensor-core GEMM:
//   C[b][i,j] = scale * sum_k A[i,k]*B[k,j] (+bias[i]) (+resid[b][i,j])
// A elem at A + b*sAb + i*sAi + k*sAk ; B elem at B + b*sBb + k*sBk + j*sBj
// C row-major MxN per batch, batch stride sCb. M,N multiples of 128; K multiple of 16.
// Block tile 128x128x16, 256 threads (8 warps, each 64x32 via m16n8k8).
#define SPAD 136   // smem row stride in words: 8 mod 32 -> conflict-free fragment loads

__global__ __launch_bounds__(256, 2)
void tgemm(const float* __restrict__ A, const float* __restrict__ Bm,
           float* __restrict__ Cm,
           const float* __restrict__ bias, const float* __restrict__ resid,
           int M, int Nn, int K,
           long sAi, long sAk, long sAb,
           long sBk, long sBj, long sBb,
           long sCb, long sRb, float scale) {
    __shared__ uint32_t As[16][SPAD];
    __shared__ uint32_t Bs[16][SPAD];

    const int b  = blockIdx.z;
    const int i0 = blockIdx.y * 128;
    const int j0 = blockIdx.x * 128;
    const float* Ab = A + (long)b * sAb;
    const float* Bb = Bm + (long)b * sBb;

    const int tid = threadIdx.x;
    const int wid = tid >> 5;
    const int lane = tid & 31;
    const int g  = lane >> 2;   // groupID 0..7
    const int tl = lane & 3;    // thread-in-group 0..3
    const int mWarp = (wid & 1) * 64;   // 2 warp rows
    const int nWarp = (wid >> 1) * 32;  // 4 warp cols

    // Load index mappings chosen so the unit-stride axis is lane-contiguous.
    const bool aK1 = (sAk == 1);
    const bool bJ1 = (sBj == 1);

    float c[4][4][4];
#pragma unroll
    for (int mt = 0; mt < 4; mt++)
#pragma unroll
        for (int nt = 0; nt < 4; nt++)
#pragma unroll
            for (int r = 0; r < 4; r++) c[mt][nt][r] = 0.f;

    uint32_t ra[8], rb[8];

    // prologue loads (k0 = 0)
#pragma unroll
    for (int l = 0; l < 8; l++) {
        int idx = l * 256 + tid;
        int ii, kk;
        if (aK1) { kk = idx & 15; ii = idx >> 4; } else { ii = idx & 127; kk = idx >> 7; }
        ra[l] = f2tf32(Ab[(long)(i0 + ii) * sAi + (long)kk * sAk]);
        int jj, kb;
        if (bJ1) { jj = idx & 127; kb = idx >> 7; } else { kb = idx & 15; jj = idx >> 4; }
        rb[l] = f2tf32(Bb[(long)kb * sBk + (long)(j0 + jj) * sBj]);
    }

    for (int k0 = 0; k0 < K; k0 += 16) {
        // store staged regs to smem
#pragma unroll
        for (int l = 0; l < 8; l++) {
            int idx = l * 256 + tid;
            int ii, kk;
            if (aK1) { kk = idx & 15; ii = idx >> 4; } else { ii = idx & 127; kk = idx >> 7; }
            As[kk][ii] = ra[l];
            int jj, kb;
            if (bJ1) { jj = idx & 127; kb = idx >> 7; } else { kb = idx & 15; jj = idx >> 4; }
            Bs[kb][jj] = rb[l];
        }
        __syncthreads();

        // issue next tile's global loads (overlap with compute)
        if (k0 + 16 < K) {
            int kn = k0 + 16;
#pragma unroll
            for (int l = 0; l < 8; l++) {
                int idx = l * 256 + tid;
                int ii, kk;
                if (aK1) { kk = idx & 15; ii = idx >> 4; } else { ii = idx & 127; kk = idx >> 7; }
                ra[l] = f2tf32(Ab[(long)(i0 + ii) * sAi + (long)(kn + kk) * sAk]);
                int jj, kb;
                if (bJ1) { jj = idx & 127; kb = idx >> 7; } else { kb = idx & 15; jj = idx >> 4; }
                rb[l] = f2tf32(Bb[(long)(kn + kb) * sBk + (long)(j0 + jj) * sBj]);
            }
        }

        // compute from smem: 2 k-steps of 8
#pragma unroll
        for (int ks = 0; ks < 2; ks++) {
            const int kk = ks * 8;
            uint32_t af[4][4];
#pragma unroll
            for (int mt = 0; mt < 4; mt++) {
                int m = mWarp + mt * 16;
                af[mt][0] = As[kk + tl][m + g];
                af[mt][1] = As[kk + tl][m + g + 8];
                af[mt][2] = As[kk + tl + 4][m + g];
                af[mt][3] = As[kk + tl + 4][m + g + 8];
            }
            uint32_t bf[4][2];
#pragma unroll
            for (int nt = 0; nt < 4; nt++) {
                int n = nWarp + nt * 8;
                bf[nt][0] = Bs[kk + tl][n + g];
                bf[nt][1] = Bs[kk + tl + 4][n + g];
            }
#pragma unroll
            for (int mt = 0; mt < 4; mt++)
#pragma unroll
                for (int nt = 0; nt < 4; nt++)
                    mma_tf32(c[mt][nt], af[mt][0], af[mt][1], af[mt][2], af[mt][3],
                             bf[nt][0], bf[nt][1]);
        }
        __syncthreads();
    }

    // epilogue
    float* Cb = Cm + (long)b * sCb;
    const float* Rb = resid ? resid + (long)b * sRb : nullptr;
#pragma unroll
    for (int mt = 0; mt < 4; mt++) {
        int r0 = i0 + mWarp + mt * 16 + g;
        int r1 = r0 + 8;
        float bv0 = bias ? bias[r0] : 0.f;
        float bv1 = bias ? bias[r1] : 0.f;
#pragma unroll
        for (int nt = 0; nt < 4; nt++) {
            int j = j0 + nWarp + nt * 8 + 2 * tl;
            float2 v0, v1;
            v0.x = c[mt][nt][0] * scale + bv0;
            v0.y = c[mt][nt][1] * scale + bv0;
            v1.x = c[mt][nt][2] * scale + bv1;
            v1.y = c[mt][nt][3] * scale + bv1;
            if (Rb) {
                const float2 q0 = *(const float2*)&Rb[(long)r0 * Nn + j];
                const float2 q1 = *(const float2*)&Rb[(long)r1 * Nn + j];
                v0.x += q0.x; v0.y += q0.y;
                v1.x += q1.x; v1.y += q1.y;
            }
            *(float2*)&Cb[(long)r0 * Nn + j] = v0;
            *(float2*)&Cb[(long)r1 * Nn + j] = v1;
        }
    }
}

__global__ void softmax_kernel(float* __restrict__ attn) {
    float* row = attn + (long)blockIdx.x * NPIX;
    int t = threadIdx.x;  // 256 threads, 4 elems each
    float v[4];
    float mx = -1e30f;
#pragma unroll
    for (int l = 0; l < 4; l++) { v[l] = row[t + l * 256]; mx = fmaxf(mx, v[l]); }
    __shared__ float sh[256];
    sh[t] = mx; __syncthreads();
    for (int st = 128; st > 0; st >>= 1) {
        if (t < st) sh[t] = fmaxf(sh[t], sh[t + st]);
        __syncthreads();
    }
    mx = sh[0]; __syncthreads();
    float sum = 0.f;
#pragma unroll
    for (int l = 0; l < 4; l++) { v[l] = __expf(v[l] - mx); sum += v[l]; }
    sh[t] = sum; __syncthreads();
    for (int st = 128; st > 0; st >>= 1) {
        if (t < st) sh[t] += sh[t + st];
        __syncthreads();
    }
    float inv = 1.f / sh[0];
#pragma unroll
    for (int l = 0; l < 4; l++) row[t + l * 256] = v[l] * inv;
}

extern "C" void kernel_launch(void* const* d_in, const int* in_sizes, int n_in,
                              void* d_out, int out_size) {
    const float* x     = (const float*)d_in[0];
    const float* gn_w  = (const float*)d_in[1];
    const float* gn_b  = (const float*)d_in[2];
    const float* qkv_w = (const float*)d_in[3];
    const float* qkv_b = (const float*)d_in[4];
    const float* out_w = (const float*)d_in[5];
    const float* out_b = (const float*)d_in[6];
    float* out = (float*)d_out;

    float *h, *qkv, *attn, *o;
    cudaGetSymbolAddress((void**)&h, g_h);
    cudaGetSymbolAddress((void**)&qkv, g_qkv);
    cudaGetSymbolAddress((void**)&attn, g_attn);
    cudaGetSymbolAddress((void**)&o, g_o);

    const long sH  = (long)CCH * NPIX;       // 512*1024
    const long sQ  = (long)3 * CCH * NPIX;   // 1536*1024
    const long sAt = (long)NPIX * NPIX;      // 1024*1024

    // 1) GroupNorm
    groupnorm_kernel<<<BSZ * NG, 256>>>(x, gn_w, gn_b, h);

    // 2) QKV = qkv_w[1536,512] @ h[b][512,1024] + qkv_b
    tgemm<<<dim3(NPIX / 128, (3 * CCH) / 128, BSZ), 256>>>(
        qkv_w, h, qkv, qkv_b, nullptr,
        3 * CCH, NPIX, CCH,
        /*A*/ 512, 1, 0,
        /*B*/ 1024, 1, sH,
        /*C*/ sQ, 0, 1.0f);

    // 3) scores[n,m] = (1/sqrt(C)) * sum_c q[c,n]*k[c,m]
    tgemm<<<dim3(NPIX / 128, NPIX / 128, BSZ), 256>>>(
        qkv /*q*/, qkv + (long)CCH * NPIX /*k*/, attn, nullptr, nullptr,
        NPIX, NPIX, CCH,
        /*A: i=n stride 1, k=c stride 1024*/ 1, 1024, sQ,
        /*B: k=c stride 1024, j=m stride 1*/ 1024, 1, sQ,
        /*C*/ sAt, 0, 1.0f / sqrtf((float)CCH));

    // 4) row softmax over m
    softmax_kernel<<<BSZ * NPIX, 256>>>(attn);

    // 5) o[c,n] = sum_m v[c,m] * attn[n,m]
    tgemm<<<dim3(NPIX / 128, CCH / 128, BSZ), 256>>>(
        qkv + 2L * CCH * NPIX /*v*/, attn, o, nullptr, nullptr,
        CCH, NPIX, NPIX,
        /*A: i=c stride 1024, k=m stride 1*/ 1024, 1, sQ,
        /*B: k=m stride 1, j=n stride 1024*/ 1, 1024, sAt,
        /*C*/ sH, 0, 1.0f);

    // 6) out = x + out_w[512,512] @ o[b][512,1024] + out_b
    tgemm<<<dim3(NPIX / 128, CCH / 128, BSZ), 256>>>(
        out_w, o, out, out_b, x,
        CCH, NPIX, CCH,
        /*A*/ 512, 1, 0,
        /*B*/ 1024, 1, sH,
        /*C*/ sH, sH, 1.0f);
}

// round 3
// speedup vs baseline: 7.2103x; 2.7870x over previous
#include <cuda_runtime.h>
#include <math.h>
#include <stdint.h>

#define BSZ 16
#define CCH 512
#define NPIX 1024
#define NG 32

// Scratch (allocation-free rule => __device__ globals)
__device__ float g_h[(long)BSZ * CCH * NPIX];          // 33.5 MB
__device__ float g_qkv[(long)BSZ * 3 * CCH * NPIX];    // 100 MB
__device__ float g_attn[(long)BSZ * NPIX * NPIX];      // 67 MB
__device__ float g_o[(long)BSZ * CCH * NPIX];          // 33.5 MB

__global__ void groupnorm_kernel(const float* __restrict__ x,
                                 const float* __restrict__ w,
                                 const float* __restrict__ bb,
                                 float* __restrict__ h) {
    int blk = blockIdx.x;            // b*NG + g
    int b = blk / NG, g = blk % NG;
    const int CPG = CCH / NG;        // 16
    const int LEN = CPG * NPIX;      // 16384
    const float* xp = x + ((long)b * CCH + g * CPG) * NPIX;
    float* hp = h + ((long)b * CCH + g * CPG) * NPIX;

    float s = 0.f, s2 = 0.f;
    for (int i = threadIdx.x; i < LEN; i += blockDim.x) {
        float v = xp[i];
        s += v; s2 += v * v;
    }
    __shared__ float sh_s[256], sh_s2[256];
    sh_s[threadIdx.x] = s; sh_s2[threadIdx.x] = s2;
    __syncthreads();
    for (int st = 128; st > 0; st >>= 1) {
        if (threadIdx.x < st) {
            sh_s[threadIdx.x]  += sh_s[threadIdx.x + st];
            sh_s2[threadIdx.x] += sh_s2[threadIdx.x + st];
        }
        __syncthreads();
    }
    float mean = sh_s[0] / (float)LEN;
    float var  = sh_s2[0] / (float)LEN - mean * mean;
    float inv  = rsqrtf(var + 1e-5f);
    for (int i = threadIdx.x; i < LEN; i += blockDim.x) {
        int c = g * CPG + (i >> 10);
        hp[i] = (xp[i] - mean) * inv * w[c] + bb[c];
    }
}

__device__ __forceinline__ void mma_tf32(float* c,
                                         uint32_t a0, uint32_t a1, uint32_t a2, uint32_t a3,
                                         uint32_t b0, uint32_t b1) {
    asm volatile(
        "mma.sync.aligned.m16n8k8.row.col.f32.tf32.tf32.f32 "
        "{%0,%1,%2,%3}, {%4,%5,%6,%7}, {%8,%9}, {%0,%1,%2,%3};\n"
        : "+f"(c[0]), "+f"(c[1]), "+f"(c[2]), "+f"(c[3])
        : "r"(a0), "r"(a1), "r"(a2), "r"(a3), "r"(b0), "r"(b1));
}

__device__ __forceinline__ void cpa16(uint32_t saddr, const float* g) {
    asm volatile("cp.async.cg.shared.global [%0], [%1], 16;\n" :: "r"(saddr), "l"(g));
}
__device__ __forceinline__ void cp_commit() {
    asm volatile("cp.async.commit_group;\n");
}
__device__ __forceinline__ void cp_wait2() {
    asm volatile("cp.async.wait_group 2;\n");
}

// Per-stage smem layout (in 32-bit words):
//  A operand: if AK1 (k contiguous): [128 rows][KPAD=20]  else [16 k][IPAD=136]
//  B operand: if BJ1 (j contiguous): [16 k][IPAD=136]     else [128 rows][KPAD=20]
#define KPAD 20
#define IPAD 136
#define OP_WORDS 2560                  // max(128*20, 16*136) = 2560
#define STAGE_WORDS (2 * OP_WORDS)     // A + B
#define NSTAGE 4
#define SMEM_BYTES (NSTAGE * STAGE_WORDS * 4)   // 81920 B

// Generic batched tf32 tensor-core GEMM:
//   C[b][i,j] = scale * sum_k A[i,k]*B[k,j] (+bias[i]) (+resid[b][i,j])
// Block tile 128x128x16, 256 threads (8 warps, each 64x32 via m16n8k8).
// 4-stage cp.async pipeline, 3 groups in flight.
template<bool AK1, bool BJ1>
__global__ __launch_bounds__(256, 2)
void tgemm(const float* __restrict__ A, const float* __restrict__ Bm,
           float* __restrict__ Cm,
           const float* __restrict__ bias, const float* __restrict__ resid,
           int M, int Nn, int K,
           long sAi, long sAk, long sAb,
           long sBk, long sBj, long sBb,
           long sCb, long sRb, float scale) {
    extern __shared__ uint32_t sm[];
    uint32_t smbase;
    {
        void* p = (void*)sm;
        smbase = (uint32_t)__cvta_generic_to_shared(p);
    }

    const int b  = blockIdx.z;
    const int i0 = blockIdx.y * 128;
    const int j0 = blockIdx.x * 128;
    const float* Ab = A + (long)b * sAb;
    const float* Bb = Bm + (long)b * sBb;

    const int tid  = threadIdx.x;
    const int wid  = tid >> 5;
    const int lane = tid & 31;
    const int g    = lane >> 2;   // 0..7
    const int tl   = lane & 3;    // 0..3
    const int mWarp = (wid & 1) * 64;
    const int nWarp = (wid >> 1) * 32;

    const int KT = K >> 4;

    // Per-thread load descriptors (2 x 16B chunks per operand per stage)
    // A chunks
    int a_row[2], a_off[2];   // row index within tile, k- or i-offset
    // B chunks
    int b_row[2], b_off[2];

#pragma unroll
    for (int l = 0; l < 2; l++) {
        int idx = l * 256 + tid;
        if (AK1) { a_row[l] = idx >> 2; a_off[l] = (idx & 3) * 4; }   // row=i (128), off=k chunk
        else     { a_row[l] = idx >> 5; a_off[l] = (idx & 31) * 4; }  // row=k (16), off=i chunk
        if (BJ1) { b_row[l] = idx >> 5; b_off[l] = (idx & 31) * 4; }  // row=k (16), off=j chunk
        else     { b_row[l] = idx >> 2; b_off[l] = (idx & 3) * 4; }   // row=j (128), off=k chunk
    }

    auto issue = [&](int ki) {
        if (ki < KT) {
            const int k0 = ki << 4;
            uint32_t abase = smbase + ((ki & (NSTAGE - 1)) * STAGE_WORDS) * 4;
            uint32_t bbase = abase + OP_WORDS * 4;
#pragma unroll
            for (int l = 0; l < 2; l++) {
                const float* gp;
                uint32_t sa;
                if (AK1) {
                    gp = Ab + (long)(i0 + a_row[l]) * sAi + (long)(k0 + a_off[l]);
                    sa = abase + (a_row[l] * KPAD + a_off[l]) * 4;
                } else {
                    gp = Ab + (long)(k0 + a_row[l]) * sAk + (long)(i0 + a_off[l]);
                    sa = abase + (a_row[l] * IPAD + a_off[l]) * 4;
                }
                cpa16(sa, gp);
                if (BJ1) {
                    gp = Bb + (long)(k0 + b_row[l]) * sBk + (long)(j0 + b_off[l]);
                    sa = bbase + (b_row[l] * IPAD + b_off[l]) * 4;
                } else {
                    gp = Bb + (long)(j0 + b_row[l]) * sBj + (long)(k0 + b_off[l]);
                    sa = bbase + (b_row[l] * KPAD + b_off[l]) * 4;
                }
                cpa16(sa, gp);
            }
        }
        cp_commit();
    };

    float c[4][4][4];
#pragma unroll
    for (int mt = 0; mt < 4; mt++)
#pragma unroll
        for (int nt = 0; nt < 4; nt++)
#pragma unroll
            for (int r = 0; r < 4; r++) c[mt][nt][r] = 0.f;

    issue(0); issue(1); issue(2);

    for (int i = 0; i < KT; i++) {
        cp_wait2();
        __syncthreads();
        issue(i + 3);

        const uint32_t* As = sm + (i & (NSTAGE - 1)) * STAGE_WORDS;
        const uint32_t* Bs = As + OP_WORDS;

#pragma unroll
        for (int ks = 0; ks < 2; ks++) {
            const int kk = ks * 8;
            uint32_t af[4][4];
#pragma unroll
            for (int mt = 0; mt < 4; mt++) {
                const int m = mWarp + mt * 16;
                if (AK1) {
                    af[mt][0] = As[(m + g) * KPAD + kk + tl];
                    af[mt][1] = As[(m + g + 8) * KPAD + kk + tl];
                    af[mt][2] = As[(m + g) * KPAD + kk + tl + 4];
                    af[mt][3] = As[(m + g + 8) * KPAD + kk + tl + 4];
                } else {
                    af[mt][0] = As[(kk + tl) * IPAD + m + g];
                    af[mt][1] = As[(kk + tl) * IPAD + m + g + 8];
                    af[mt][2] = As[(kk + tl + 4) * IPAD + m + g];
                    af[mt][3] = As[(kk + tl + 4) * IPAD + m + g + 8];
                }
            }
            uint32_t bf[4][2];
#pragma unroll
            for (int nt = 0; nt < 4; nt++) {
                const int n = nWarp + nt * 8;
                if (BJ1) {
                    bf[nt][0] = Bs[(kk + tl) * IPAD + n + g];
                    bf[nt][1] = Bs[(kk + tl + 4) * IPAD + n + g];
                } else {
                    bf[nt][0] = Bs[(n + g) * KPAD + kk + tl];
                    bf[nt][1] = Bs[(n + g) * KPAD + kk + tl + 4];
                }
            }
#pragma unroll
            for (int mt = 0; mt < 4; mt++)
#pragma unroll
                for (int nt = 0; nt < 4; nt++)
                    mma_tf32(c[mt][nt], af[mt][0], af[mt][1], af[mt][2], af[mt][3],
                             bf[nt][0], bf[nt][1]);
        }
    }

    // epilogue
    float* Cb = Cm + (long)b * sCb;
    const float* Rb = resid ? resid + (long)b * sRb : nullptr;
#pragma unroll
    for (int mt = 0; mt < 4; mt++) {
        int r0 = i0 + mWarp + mt * 16 + g;
        int r1 = r0 + 8;
        float bv0 = bias ? bias[r0] : 0.f;
        float bv1 = bias ? bias[r1] : 0.f;
#pragma unroll
        for (int nt = 0; nt < 4; nt++) {
            int j = j0 + nWarp + nt * 8 + 2 * tl;
            float2 v0, v1;
            v0.x = c[mt][nt][0] * scale + bv0;
            v0.y = c[mt][nt][1] * scale + bv0;
            v1.x = c[mt][nt][2] * scale + bv1;
            v1.y = c[mt][nt][3] * scale + bv1;
            if (Rb) {
                const float2 q0 = *(const float2*)&Rb[(long)r0 * Nn + j];
                const float2 q1 = *(const float2*)&Rb[(long)r1 * Nn + j];
                v0.x += q0.x; v0.y += q0.y;
                v1.x += q1.x; v1.y += q1.y;
            }
            *(float2*)&Cb[(long)r0 * Nn + j] = v0;
            *(float2*)&Cb[(long)r1 * Nn + j] = v1;
        }
    }
}

__global__ void softmax_kernel(float* __restrict__ attn) {
    float* row = attn + (long)blockIdx.x * NPIX;
    int t = threadIdx.x;  // 256 threads, 4 elems each
    float v[4];
    float mx = -1e30f;
#pragma unroll
    for (int l = 0; l < 4; l++) { v[l] = row[t + l * 256]; mx = fmaxf(mx, v[l]); }
    __shared__ float sh[256];
    sh[t] = mx; __syncthreads();
    for (int st = 128; st > 0; st >>= 1) {
        if (t < st) sh[t] = fmaxf(sh[t], sh[t + st]);
        __syncthreads();
    }
    mx = sh[0]; __syncthreads();
    float sum = 0.f;
#pragma unroll
    for (int l = 0; l < 4; l++) { v[l] = __expf(v[l] - mx); sum += v[l]; }
    sh[t] = sum; __syncthreads();
    for (int st = 128; st > 0; st >>= 1) {
        if (t < st) sh[t] += sh[t + st];
        __syncthreads();
    }
    float inv = 1.f / sh[0];
#pragma unroll
    for (int l = 0; l < 4; l++) row[t + l * 256] = v[l] * inv;
}

extern "C" void kernel_launch(void* const* d_in, const int* in_sizes, int n_in,
                              void* d_out, int out_size) {
    const float* x     = (const float*)d_in[0];
    const float* gn_w  = (const float*)d_in[1];
    const float* gn_b  = (const float*)d_in[2];
    const float* qkv_w = (const float*)d_in[3];
    const float* qkv_b = (const float*)d_in[4];
    const float* out_w = (const float*)d_in[5];
    const float* out_b = (const float*)d_in[6];
    float* out = (float*)d_out;

    float *h, *qkv, *attn, *o;
    cudaGetSymbolAddress((void**)&h, g_h);
    cudaGetSymbolAddress((void**)&qkv, g_qkv);
    cudaGetSymbolAddress((void**)&attn, g_attn);
    cudaGetSymbolAddress((void**)&o, g_o);

    static bool attr_done = false;
    if (!attr_done) {
        cudaFuncSetAttribute(tgemm<true, true>,
                             cudaFuncAttributeMaxDynamicSharedMemorySize, SMEM_BYTES);
        cudaFuncSetAttribute(tgemm<false, true>,
                             cudaFuncAttributeMaxDynamicSharedMemorySize, SMEM_BYTES);
        cudaFuncSetAttribute(tgemm<true, false>,
                             cudaFuncAttributeMaxDynamicSharedMemorySize, SMEM_BYTES);
        attr_done = true;
    }

    const long sH  = (long)CCH * NPIX;       // 512*1024
    const long sQ  = (long)3 * CCH * NPIX;   // 1536*1024
    const long sAt = (long)NPIX * NPIX;      // 1024*1024

    // 1) GroupNorm
    groupnorm_kernel<<<BSZ * NG, 256>>>(x, gn_w, gn_b, h);

    // 2) QKV = qkv_w[1536,512] @ h[b][512,1024] + qkv_b
    tgemm<true, true><<<dim3(NPIX / 128, (3 * CCH) / 128, BSZ), 256, SMEM_BYTES>>>(
        qkv_w, h, qkv, qkv_b, nullptr,
        3 * CCH, NPIX, CCH,
        /*A*/ 512, 1, 0,
        /*B*/ 1024, 1, sH,
        /*C*/ sQ, 0, 1.0f);

    // 3) scores[n,m] = (1/sqrt(C)) * sum_c q[c,n]*k[c,m]
    tgemm<false, true><<<dim3(NPIX / 128, NPIX / 128, BSZ), 256, SMEM_BYTES>>>(
        qkv /*q*/, qkv + (long)CCH * NPIX /*k*/, attn, nullptr, nullptr,
        NPIX, NPIX, CCH,
        /*A: i=n stride 1, k=c stride 1024*/ 1, 1024, sQ,
        /*B: k=c stride 1024, j=m stride 1*/ 1024, 1, sQ,
        /*C*/ sAt, 0, 1.0f / sqrtf((float)CCH));

    // 4) row softmax over m
    softmax_kernel<<<BSZ * NPIX, 256>>>(attn);

    // 5) o[c,n] = sum_m v[c,m] * attn[n,m]
    tgemm<true, false><<<dim3(NPIX / 128, CCH / 128, BSZ), 256, SMEM_BYTES>>>(
        qkv + 2L * CCH * NPIX /*v*/, attn, o, nullptr, nullptr,
        CCH, NPIX, NPIX,
        /*A: i=c stride 1024, k=m stride 1*/ 1024, 1, sQ,
        /*B: k=m stride 1, j=n stride 1024*/ 1, 1024, sAt,
        /*C*/ sH, 0, 1.0f);

    // 6) out = x + out_w[512,512] @ o[b][512,1024] + out_b
    tgemm<true, true><<<dim3(NPIX / 128, CCH / 128, BSZ), 256, SMEM_BYTES>>>(
        out_w, o, out, out_b, x,
        CCH, NPIX, CCH,
        /*A*/ 512, 1, 0,
        /*B*/ 1024, 1, sH,
        /*C*/ sH, sH, 1.0f);
}